// round 11
// baseline (speedup 1.0000x reference)
#include <cuda_runtime.h>
#include <cstdint>

#define Bn 64
#define Fn 64
#define Cn 8
#define Pn 16384              // pixels per image (128x128)
#define Kn 10                 // steps_to_run
#define BP (Bn * Pn)          // 1048576 total pixels
#define THR 256               // threads per CTA
#define QF4 1024              // float4s per CTA quarter (4096 px)

// Scratch (device globals: allocation-free per harness rules)
// colour is CHANNEL-MAJOR: g_colour[((b*Cn)+c)*Pn + p]  (33.5 MB)
__device__ float g_colour[(size_t)Bn * Cn * Pn];
__device__ float g_stage[(size_t)(Kn - 1) * BP];  // [k][b*p]  37.7 MB (streamed)

// ---------------------------------------------------------------------------
__device__ __forceinline__ uint32_t smem_u32(const void* p) {
    uint32_t a;
    asm("{ .reg .u64 t; cvta.to.shared.u64 t, %1; cvt.u32.u64 %0, t; }"
        : "=r"(a) : "l"(p));
    return a;
}
__device__ __forceinline__ float ld_dsmem_f32(uint32_t saddr, uint32_t rank) {
    float v;
    asm volatile("{ .reg .b32 r; mapa.shared::cluster.u32 r, %1, %2; "
                 "ld.shared::cluster.f32 %0, [r]; }"
                 : "=f"(v) : "r"(saddr), "r"(rank));
    return v;
}
__device__ __forceinline__ int ld_dsmem_s32(uint32_t saddr, uint32_t rank) {
    int v;
    asm volatile("{ .reg .b32 r; mapa.shared::cluster.u32 r, %1, %2; "
                 "ld.shared::cluster.u32 %0, [r]; }"
                 : "=r"(v) : "r"(saddr), "r"(rank));
    return v;
}

// ---------------------------------------------------------------------------
// Kernel 1: 1x1 conv + gate + coord channels -> g_colour (channel-major).
// ---------------------------------------------------------------------------
__global__ void conv_kernel(const float4* __restrict__ feat,
                            const float* __restrict__ w,
                            const float* __restrict__ bias,
                            const float* __restrict__ gate) {
    __shared__ float ws[Cn * Fn];
    __shared__ float bs[Cn];
    int tid = threadIdx.x;
    for (int i = tid; i < Cn * Fn; i += blockDim.x) ws[i] = w[i];
    if (tid < Cn) bs[tid] = bias[tid];
    __syncthreads();

    int gidx = blockIdx.x * blockDim.x + tid;   // 0 .. BP/4-1
    int b = gidx >> 12;
    int q = gidx & 4095;

    const float4* fb = feat + (size_t)b * (Fn * Pn / 4) + q;

    float4 acc[Cn];
#pragma unroll
    for (int c = 0; c < Cn; c++) {
        float bb = bs[c];
        acc[c] = make_float4(bb, bb, bb, bb);
    }

#pragma unroll 8
    for (int f = 0; f < Fn; f++) {
        float4 v = __ldcs(&fb[(size_t)f * (Pn / 4)]);   // stream features
#pragma unroll
        for (int c = 0; c < Cn; c++) {
            float wc = ws[c * Fn + f];
            acc[c].x += v.x * wc;
            acc[c].y += v.y * wc;
            acc[c].z += v.z * wc;
            acc[c].w += v.w * wc;
        }
    }

    float g = gate[0];
#pragma unroll
    for (int c = 0; c < Cn; c++) {
        acc[c].x *= g; acc[c].y *= g; acc[c].z *= g; acc[c].w *= g;
    }

    int p0 = q << 2;
    int h  = p0 >> 7;
    int wc0 = p0 & 127;
    const float step = 2.0f / 127.0f;
    float yy = -1.0f + step * (float)h;
    acc[6].x += yy; acc[6].y += yy; acc[6].z += yy; acc[6].w += yy;
    float xx = -1.0f + step * (float)wc0;
    acc[7].x += xx;
    acc[7].y += xx + step;
    acc[7].z += xx + 2.0f * step;
    acc[7].w += xx + 3.0f * step;

    float4* cb = (float4*)g_colour;
#pragma unroll
    for (int c = 0; c < Cn; c++)
        cb[((size_t)b * Cn + c) * (Pn / 4) + q] = acc[c];
}

// ---------------------------------------------------------------------------
// Kernel 2: persistent step loop. 256 CTAs x 256 thr, cluster(4) = one batch.
// Each CTA owns a quarter (4096 px = 16 px/thread). k-loop kept ROLLED
// (#pragma unroll 1) so the body fits I$ (L0/L1.5).
// ---------------------------------------------------------------------------
__global__ void __launch_bounds__(THR, 2) __cluster_dims__(4, 1, 1)
step_loop_kernel(float* __restrict__ out, const float4* __restrict__ rp4,
                 const float* __restrict__ log_sigma) {
    __shared__ float s_wv[8];
    __shared__ int   s_wp[8];
    __shared__ float s_slotv[2];
    __shared__ int   s_sloti[2];
    __shared__ int   s_pstar;
    __shared__ float s_seed[Cn];

    const int tid = threadIdx.x;
    const int b = blockIdx.x >> 2;              // batch (cluster id)
    uint32_t rank;
    asm("mov.u32 %0, %%cluster_ctarank;" : "=r"(rank));

    const float invsig = expf(-log_sigma[0]);
    const float LOG2E = 1.4426950408889634f;
    const float L_LO  = -4.6051702f;      // log(0.01f)
    const float L_HI  = -0.010050326f;    // log(0.99f)

    const int base4 = (int)rank * QF4 + tid;    // float4 index in batch plane
    const float4* colour4 = (const float4*)g_colour;
    float4* stage4 = (float4*)g_stage;

    float4 rp[4];
#pragma unroll
    for (int j = 0; j < 4; j++)
        rp[j] = __ldg(&rp4[b * 4096 + base4 + j * THR]);

    float ls[16];
#pragma unroll
    for (int i = 0; i < 16; i++) ls[i] = 0.0f;
    float lm9[16];

    // k=0 argmax candidate straight from rand_pixel (scope == 1)
    float vl = -3.402823466e38f; int pl = 0;
#pragma unroll
    for (int j = 0; j < 4; j++) {
        int pbase = (base4 + j * THR) << 2;    // ascending in j
        float vv[4] = {rp[j].x, rp[j].y, rp[j].z, rp[j].w};
#pragma unroll
        for (int i = 0; i < 4; i++)
            if (vv[i] > vl) { vl = vv[i]; pl = pbase + i; }   // keep first idx
    }

#pragma unroll 1
    for (int k = 0; k < Kn; k++) {
        // ---- CTA argmax reduce of (vl, pl), first-index tie-break ----
#pragma unroll
        for (int o = 16; o; o >>= 1) {
            float ov = __shfl_down_sync(0xFFFFFFFFu, vl, o);
            int   op = __shfl_down_sync(0xFFFFFFFFu, pl, o);
            if (ov > vl || (ov == vl && op < pl)) { vl = ov; pl = op; }
        }
        if ((tid & 31) == 0) { s_wv[tid >> 5] = vl; s_wp[tid >> 5] = pl; }
        __syncthreads();
        if (tid < 32) {
            float v2 = (tid < 8) ? s_wv[tid] : -3.402823466e38f;
            int   p2 = (tid < 8) ? s_wp[tid] : 0x7FFFFFFF;
#pragma unroll
            for (int o = 4; o; o >>= 1) {
                float ov = __shfl_down_sync(0xFFFFFFFFu, v2, o);
                int   op = __shfl_down_sync(0xFFFFFFFFu, p2, o);
                if (ov > v2 || (ov == v2 && op < p2)) { v2 = ov; p2 = op; }
            }
            if (tid == 0) { s_slotv[k & 1] = v2; s_sloti[k & 1] = p2; }
        }
        __syncthreads();

        // ---- exchange CTA winners across the 4-CTA cluster ----
        asm volatile("barrier.cluster.arrive.aligned;" ::: "memory");
        asm volatile("barrier.cluster.wait.aligned;" ::: "memory");
        if (tid == 0) {
            int par = k & 1;
            float bv = s_slotv[par];
            int   bp = s_sloti[par];
            uint32_t av = smem_u32(&s_slotv[par]);
            uint32_t ai = smem_u32(&s_sloti[par]);
#pragma unroll
            for (uint32_t r = 0; r < 4; r++) {
                if (r == rank) continue;
                float pv = ld_dsmem_f32(av, r);
                int   pi = ld_dsmem_s32(ai, r);
                if (pv > bv || (pv == bv && pi < bp)) { bv = pv; bp = pi; }
            }
            s_pstar = bp;
        }
        __syncthreads();
        if (tid < Cn)
            s_seed[tid] = g_colour[((size_t)b * Cn + tid) * Pn + s_pstar];
        __syncthreads();

        float sd[Cn];
#pragma unroll
        for (int c = 0; c < Cn; c++) sd[c] = s_seed[c];

        const int last = (k == Kn - 1);
        vl = -3.402823466e38f; pl = 0;

        // ---- pixel loop: 16 px/thread, channel-major colour from L2 ----
#pragma unroll
        for (int j = 0; j < 4; j++) {
            int f4 = base4 + j * THR;

            float4 col[Cn];
#pragma unroll
            for (int c = 0; c < Cn; c++)
                col[c] = __ldg(&colour4[((size_t)b * Cn + c) * 4096 + f4]);

            float4 d2 = make_float4(0.f, 0.f, 0.f, 0.f);
#pragma unroll
            for (int c = 0; c < Cn; c++) {
                float sc = sd[c];
                float tx = col[c].x - sc; d2.x += tx * tx;
                float ty = col[c].y - sc; d2.y += ty * ty;
                float tz = col[c].z - sc; d2.z += tz * tz;
                float tw = col[c].w - sc; d2.w += tw * tw;
            }

            int pbase = f4 << 2;
            float dd[4] = {d2.x, d2.y, d2.z, d2.w};
            float rr[4] = {rp[j].x, rp[j].y, rp[j].z, rp[j].w};
            float lmv[4];
#pragma unroll
            for (int i = 0; i < 4; i++) {
                float t = -(dd[i] * invsig);
                float alpha = exp2f(t * LOG2E);
                alpha = fminf(fmaxf(alpha, 0.01f), 0.99f);
                float log_a = fminf(fmaxf(t, L_LO), L_HI);
                int li = j * 4 + i;
                float lsv = ls[li];
                lmv[i] = lsv + log_a;
                lsv += logf(1.0f - alpha);
                ls[li] = lsv;
                if (!last) {
                    float v = rr[i] * expf(lsv);
                    if (v > vl) { vl = v; pl = pbase + i; }   // ascending p
                } else {
                    lm9[li] = lmv[i];
                }
            }
            if (!last) {
                float4 lm4 = make_float4(lmv[0], lmv[1], lmv[2], lmv[3]);
                __stcs(&stage4[(size_t)k * (BP / 4) + b * 4096 + f4], lm4);
            }
        }
    }

    // ---- epilogue: assemble [b,p,11] output, contiguous 44B per pixel ----
#pragma unroll
    for (int j = 0; j < 4; j++) {
        int f4 = base4 + j * THR;
        int pbase = f4 << 2;
        float* op0 = out + ((size_t)b * Pn + pbase) * (Kn + 1);
        float* op1 = op0 + (Kn + 1);
        float* op2 = op1 + (Kn + 1);
        float* op3 = op2 + (Kn + 1);
#pragma unroll 1
        for (int kk = 0; kk < Kn - 1; kk++) {
            float4 s = __ldcs(&stage4[(size_t)kk * (BP / 4) + b * 4096 + f4]);
            __stcs(op0 + kk, s.x);
            __stcs(op1 + kk, s.y);
            __stcs(op2 + kk, s.z);
            __stcs(op3 + kk, s.w);
        }
        __stcs(op0 + Kn - 1, lm9[j * 4 + 0]); __stcs(op0 + Kn, ls[j * 4 + 0]);
        __stcs(op1 + Kn - 1, lm9[j * 4 + 1]); __stcs(op1 + Kn, ls[j * 4 + 1]);
        __stcs(op2 + Kn - 1, lm9[j * 4 + 2]); __stcs(op2 + Kn, ls[j * 4 + 2]);
        __stcs(op3 + Kn - 1, lm9[j * 4 + 3]); __stcs(op3 + Kn, ls[j * 4 + 3]);
    }
}

// ---------------------------------------------------------------------------
extern "C" void kernel_launch(void* const* d_in, const int* in_sizes, int n_in,
                              void* d_out, int out_size) {
    const float* features  = (const float*)d_in[0];
    const float* rand_pix  = (const float*)d_in[1];
    const float* conv_w    = (const float*)d_in[2];
    const float* conv_b    = (const float*)d_in[3];
    const float* gate      = (const float*)d_in[4];
    const float* log_sigma = (const float*)d_in[5];
    float* out = (float*)d_out;

    (void)in_sizes; (void)n_in; (void)out_size;

    conv_kernel<<<(BP / 4) / 256, 256>>>((const float4*)features,
                                         conv_w, conv_b, gate);
    step_loop_kernel<<<Bn * 4, THR>>>(out, (const float4*)rand_pix, log_sigma);
}

// round 12
// speedup vs baseline: 1.4154x; 1.4154x over previous
#include <cuda_runtime.h>
#include <cstdint>

#define Bn 64
#define Fn 64
#define Cn 8
#define Pn 16384              // pixels per image (128x128)
#define Kn 10                 // steps_to_run
#define BP (Bn * Pn)          // 1048576 total pixels
#define THR 256               // threads per CTA
#define CLW 8                 // cluster width (CTAs per batch)
#define EF4 512               // float4s per CTA eighth (2048 px)

// Scratch (device globals: allocation-free per harness rules)
// colour is CHANNEL-MAJOR: g_colour[((b*Cn)+c)*Pn + p]  (33.5 MB)
__device__ float g_colour[(size_t)Bn * Cn * Pn];
__device__ float g_stage[(size_t)Kn * BP];        // [k][b*p]  41.9 MB (streamed)

// ---------------------------------------------------------------------------
__device__ __forceinline__ uint32_t smem_u32(const void* p) {
    uint32_t a;
    asm("{ .reg .u64 t; cvta.to.shared.u64 t, %1; cvt.u32.u64 %0, t; }"
        : "=r"(a) : "l"(p));
    return a;
}
__device__ __forceinline__ float ld_dsmem_f32(uint32_t saddr, uint32_t rank) {
    float v;
    asm volatile("{ .reg .b32 r; mapa.shared::cluster.u32 r, %1, %2; "
                 "ld.shared::cluster.f32 %0, [r]; }"
                 : "=f"(v) : "r"(saddr), "r"(rank));
    return v;
}
__device__ __forceinline__ int ld_dsmem_s32(uint32_t saddr, uint32_t rank) {
    int v;
    asm volatile("{ .reg .b32 r; mapa.shared::cluster.u32 r, %1, %2; "
                 "ld.shared::cluster.u32 %0, [r]; }"
                 : "=r"(v) : "r"(saddr), "r"(rank));
    return v;
}

// ---------------------------------------------------------------------------
// Kernel 1: 1x1 conv + gate + coord channels -> g_colour (channel-major).
// ---------------------------------------------------------------------------
__global__ void conv_kernel(const float4* __restrict__ feat,
                            const float* __restrict__ w,
                            const float* __restrict__ bias,
                            const float* __restrict__ gate) {
    __shared__ float ws[Cn * Fn];
    __shared__ float bs[Cn];
    int tid = threadIdx.x;
    for (int i = tid; i < Cn * Fn; i += blockDim.x) ws[i] = w[i];
    if (tid < Cn) bs[tid] = bias[tid];
    __syncthreads();

    int gidx = blockIdx.x * blockDim.x + tid;   // 0 .. BP/4-1
    int b = gidx >> 12;
    int q = gidx & 4095;

    const float4* fb = feat + (size_t)b * (Fn * Pn / 4) + q;

    float4 acc[Cn];
#pragma unroll
    for (int c = 0; c < Cn; c++) {
        float bb = bs[c];
        acc[c] = make_float4(bb, bb, bb, bb);
    }

#pragma unroll 8
    for (int f = 0; f < Fn; f++) {
        float4 v = __ldcs(&fb[(size_t)f * (Pn / 4)]);   // stream features
#pragma unroll
        for (int c = 0; c < Cn; c++) {
            float wc = ws[c * Fn + f];
            acc[c].x += v.x * wc;
            acc[c].y += v.y * wc;
            acc[c].z += v.z * wc;
            acc[c].w += v.w * wc;
        }
    }

    float g = gate[0];
#pragma unroll
    for (int c = 0; c < Cn; c++) {
        acc[c].x *= g; acc[c].y *= g; acc[c].z *= g; acc[c].w *= g;
    }

    int p0 = q << 2;
    int h  = p0 >> 7;
    int wc0 = p0 & 127;
    const float step = 2.0f / 127.0f;
    float yy = -1.0f + step * (float)h;
    acc[6].x += yy; acc[6].y += yy; acc[6].z += yy; acc[6].w += yy;
    float xx = -1.0f + step * (float)wc0;
    acc[7].x += xx;
    acc[7].y += xx + step;
    acc[7].z += xx + 2.0f * step;
    acc[7].w += xx + 3.0f * step;

    float4* cb = (float4*)g_colour;
#pragma unroll
    for (int c = 0; c < Cn; c++)
        cb[((size_t)b * Cn + c) * (Pn / 4) + q] = acc[c];
}

// ---------------------------------------------------------------------------
// Kernel 2: persistent step loop. 512 CTAs x 256 thr, cluster(8) = one batch.
// Each CTA owns an eighth (2048 px = 8 px/thread). 4 CTAs/SM (regs<=64)
// -> 32 warps/SM, one wave; cross-cluster overlap hides sync latency.
// ---------------------------------------------------------------------------
__global__ void __launch_bounds__(THR, 4) __cluster_dims__(CLW, 1, 1)
step_loop_kernel(float* __restrict__ out, const float4* __restrict__ rp4,
                 const float* __restrict__ log_sigma) {
    __shared__ float s_wv[8];
    __shared__ int   s_wp[8];
    __shared__ float s_slotv[2];
    __shared__ int   s_sloti[2];
    __shared__ float s_seed[Cn];

    const int tid = threadIdx.x;
    const int b = blockIdx.x >> 3;              // batch (cluster id)
    uint32_t rank;
    asm("mov.u32 %0, %%cluster_ctarank;" : "=r"(rank));

    const float invsig = expf(-log_sigma[0]);
    const float LOG2E = 1.4426950408889634f;
    const float L_LO  = -4.6051702f;      // log(0.01f)
    const float L_HI  = -0.010050326f;    // log(0.99f)

    const int base4 = (int)rank * EF4 + tid;    // float4 index in batch plane
    const float4* colour4 = (const float4*)g_colour;
    float4* stage4 = (float4*)g_stage;

    float4 rp[2];
#pragma unroll
    for (int j = 0; j < 2; j++)
        rp[j] = __ldg(&rp4[b * 4096 + base4 + j * THR]);

    float ls[8];
#pragma unroll
    for (int i = 0; i < 8; i++) ls[i] = 0.0f;

    // k=0 argmax candidate straight from rand_pixel (scope == 1)
    float vl = -3.402823466e38f; int pl = 0;
#pragma unroll
    for (int j = 0; j < 2; j++) {
        int pbase = (base4 + j * THR) << 2;    // ascending in j
        float vv[4] = {rp[j].x, rp[j].y, rp[j].z, rp[j].w};
#pragma unroll
        for (int i = 0; i < 4; i++)
            if (vv[i] > vl) { vl = vv[i]; pl = pbase + i; }   // keep first idx
    }

    for (int k = 0; k < Kn; k++) {
        // ---- CTA argmax reduce of (vl, pl), first-index tie-break ----
#pragma unroll
        for (int o = 16; o; o >>= 1) {
            float ov = __shfl_down_sync(0xFFFFFFFFu, vl, o);
            int   op = __shfl_down_sync(0xFFFFFFFFu, pl, o);
            if (ov > vl || (ov == vl && op < pl)) { vl = ov; pl = op; }
        }
        if ((tid & 31) == 0) { s_wv[tid >> 5] = vl; s_wp[tid >> 5] = pl; }
        __syncthreads();
        if (tid < 32) {
            float v2 = (tid < 8) ? s_wv[tid] : -3.402823466e38f;
            int   p2 = (tid < 8) ? s_wp[tid] : 0x7FFFFFFF;
#pragma unroll
            for (int o = 4; o; o >>= 1) {
                float ov = __shfl_down_sync(0xFFFFFFFFu, v2, o);
                int   op = __shfl_down_sync(0xFFFFFFFFu, p2, o);
                if (ov > v2 || (ov == v2 && op < p2)) { v2 = ov; p2 = op; }
            }
            if (tid == 0) { s_slotv[k & 1] = v2; s_sloti[k & 1] = p2; }
        }
        __syncthreads();

        // ---- exchange CTA winners across the 8-CTA cluster (parallel) ----
        asm volatile("barrier.cluster.arrive.aligned;" ::: "memory");
        asm volatile("barrier.cluster.wait.aligned;" ::: "memory");
        if (tid < 8) {
            int par = k & 1;
            uint32_t av = smem_u32(&s_slotv[par]);
            uint32_t ai = smem_u32(&s_sloti[par]);
            // lane r reads rank r's winner
            float pv = ld_dsmem_f32(av, (uint32_t)tid);
            int   pi = ld_dsmem_s32(ai, (uint32_t)tid);
#pragma unroll
            for (int o = 4; o; o >>= 1) {
                float ov = __shfl_down_sync(0xFFu, pv, o);
                int   oi = __shfl_down_sync(0xFFu, pi, o);
                if (ov > pv || (ov == pv && oi < pi)) { pv = ov; pi = oi; }
            }
            int pwin = __shfl_sync(0xFFu, pi, 0);
            // seed gather: lane c loads channel c at winning pixel
            s_seed[tid] = g_colour[((size_t)b * Cn + tid) * Pn + pwin];
        }
        __syncthreads();

        float sd[Cn];
#pragma unroll
        for (int c = 0; c < Cn; c++) sd[c] = s_seed[c];

        const int last = (k == Kn - 1);
        vl = -3.402823466e38f; pl = 0;

        // ---- pixel loop: 8 px/thread, channel-major colour from L2 ----
#pragma unroll
        for (int j = 0; j < 2; j++) {
            int f4 = base4 + j * THR;

            float4 col[Cn];
#pragma unroll
            for (int c = 0; c < Cn; c++)
                col[c] = __ldg(&colour4[((size_t)b * Cn + c) * 4096 + f4]);

            float4 d2 = make_float4(0.f, 0.f, 0.f, 0.f);
#pragma unroll
            for (int c = 0; c < Cn; c++) {
                float sc = sd[c];
                float tx = col[c].x - sc; d2.x += tx * tx;
                float ty = col[c].y - sc; d2.y += ty * ty;
                float tz = col[c].z - sc; d2.z += tz * tz;
                float tw = col[c].w - sc; d2.w += tw * tw;
            }

            int pbase = f4 << 2;
            float dd[4] = {d2.x, d2.y, d2.z, d2.w};
            float rr[4] = {rp[j].x, rp[j].y, rp[j].z, rp[j].w};
            float lmv[4];
#pragma unroll
            for (int i = 0; i < 4; i++) {
                float t = -(dd[i] * invsig);
                float alpha = exp2f(t * LOG2E);
                alpha = fminf(fmaxf(alpha, 0.01f), 0.99f);
                float log_a = fminf(fmaxf(t, L_LO), L_HI);
                int li = j * 4 + i;
                float lsv = ls[li];
                lmv[i] = lsv + log_a;
                lsv += logf(1.0f - alpha);
                ls[li] = lsv;
                if (!last) {
                    float v = rr[i] * expf(lsv);
                    if (v > vl) { vl = v; pl = pbase + i; }   // ascending p
                }
            }
            float4 lm4 = make_float4(lmv[0], lmv[1], lmv[2], lmv[3]);
            __stcs(&stage4[(size_t)k * (BP / 4) + b * 4096 + f4], lm4);
        }
    }

    // ---- epilogue: assemble [b,p,11] output, contiguous 44B per pixel ----
#pragma unroll
    for (int j = 0; j < 2; j++) {
        int f4 = base4 + j * THR;
        int pbase = f4 << 2;
        float* op0 = out + ((size_t)b * Pn + pbase) * (Kn + 1);
        float* op1 = op0 + (Kn + 1);
        float* op2 = op1 + (Kn + 1);
        float* op3 = op2 + (Kn + 1);
#pragma unroll
        for (int kk = 0; kk < Kn; kk++) {
            float4 s = __ldcs(&stage4[(size_t)kk * (BP / 4) + b * 4096 + f4]);
            __stcs(op0 + kk, s.x);
            __stcs(op1 + kk, s.y);
            __stcs(op2 + kk, s.z);
            __stcs(op3 + kk, s.w);
        }
        __stcs(op0 + Kn, ls[j * 4 + 0]);
        __stcs(op1 + Kn, ls[j * 4 + 1]);
        __stcs(op2 + Kn, ls[j * 4 + 2]);
        __stcs(op3 + Kn, ls[j * 4 + 3]);
    }
}

// ---------------------------------------------------------------------------
extern "C" void kernel_launch(void* const* d_in, const int* in_sizes, int n_in,
                              void* d_out, int out_size) {
    const float* features  = (const float*)d_in[0];
    const float* rand_pix  = (const float*)d_in[1];
    const float* conv_w    = (const float*)d_in[2];
    const float* conv_b    = (const float*)d_in[3];
    const float* gate      = (const float*)d_in[4];
    const float* log_sigma = (const float*)d_in[5];
    float* out = (float*)d_out;

    (void)in_sizes; (void)n_in; (void)out_size;

    conv_kernel<<<(BP / 4) / 256, 256>>>((const float4*)features,
                                         conv_w, conv_b, gate);
    step_loop_kernel<<<Bn * CLW, THR>>>(out, (const float4*)rand_pix, log_sigma);
}